// round 6
// baseline (speedup 1.0000x reference)
#include <cuda_runtime.h>
#include <cstdint>

// ---------------------------------------------------------------------------
// Sparse 3x3x3 conv chain, N=1e6 voxels. R6: latency attack —
//  * next-voxel list int4 software-prefetched one iteration ahead
//  * center tap folded in as synthetic entry0 (k=13); 4-entry batches with
//    predicated gather loads issued back-to-back (MLP>=4/warp)
//  * FMA work gated by warp-uniform cnt branches (no wasted issue)
//  * chunked (CH=8 floats) register buffers -> no spills, even for 32-ch in
// ---------------------------------------------------------------------------

#define MAXN 1000000
#define NSM  148
#define LSTR 28   // per-voxel list stride (ints), 112B -> int4-aligned

__device__ int   g_mtype;                  // 0=int32, 1=uint8, 2=float32
__device__ int   g_list[(size_t)MAXN * LSTR];
__device__ float g_t32[(size_t)MAXN * 32];
__device__ float g_t8a[(size_t)MAXN * 8];
__device__ float g_t8b[(size_t)MAXN * 8];
__device__ float g_wfold[27 * 8 * 32];

// ---------------------------------------------------------------------------
__global__ void detect_mask(const unsigned int* __restrict__ m) {
    __shared__ int s_u8, s_f32;
    if (threadIdx.x == 0) { s_u8 = 0; s_f32 = 0; }
    __syncthreads();
    int loc_u8 = 0, loc_f32 = 0;
    for (int i = threadIdx.x; i < 65536; i += blockDim.x) {
        unsigned v = m[i];
        if (v == 0x3F800000u) loc_f32 = 1;
        else if (v > 1u)      loc_u8 = 1;
    }
    if (loc_u8)  atomicOr(&s_u8, 1);
    if (loc_f32) atomicOr(&s_f32, 1);
    __syncthreads();
    if (threadIdx.x == 0) g_mtype = s_f32 ? 2 : (s_u8 ? 1 : 0);
}

// Off-center entries only (k==13 handled as synthetic entry in conv).
// entry = (k<<20)|src; entry0 also carries cnt in bits [27:32).
__global__ void build_compact(const int* __restrict__ nbr,
                              const void* __restrict__ maskv, int N) {
    int n = blockIdx.x * blockDim.x + threadIdx.x;
    if (n >= N) return;
    const int mt = g_mtype;
    const int*           mi = (const int*)maskv;
    const unsigned char* mb = (const unsigned char*)maskv;
    const float*         mf = (const float*)maskv;
    int cnt = 0, first = 0;
    int* lst = &g_list[(size_t)n * LSTR];
#pragma unroll 1
    for (int k = 0; k < 27; k++) {
        if (k == 13) continue;
        size_t o = (size_t)k * N + n;
        bool on;
        if (mt == 0)      on = mi[o] != 0;
        else if (mt == 1) on = mb[o] != 0;
        else              on = mf[o] != 0.0f;
        if (on) {
            int e = (k << 20) | nbr[o];
            if (cnt == 0) first = e;
            else          lst[cnt] = e;
            cnt++;
        }
    }
    lst[0] = first | (cnt << 27);
    if (cnt < 2) lst[1] = 0;
    if (cnt < 3) lst[2] = 0;
    if (cnt < 4) lst[3] = 0;
}

// Fold tile(x,(1,4)) into Wd0: wfold[k][c][j] = sum_t Wd0[k][c+8t][j]
__global__ void fold_wd0(const float* __restrict__ Wd0) {
    int i = blockIdx.x * blockDim.x + threadIdx.x;
    if (i >= 27 * 8 * 32) return;
    int k = i / 256, rem = i % 256;
    int c = rem / 32, j = rem % 32;
    float s = 0.f;
#pragma unroll
    for (int t = 0; t < 4; t++) s += Wd0[k * 1024 + (c + 8 * t) * 32 + j];
    g_wfold[i] = s;
}

// ---------------------------------------------------------------------------
// Warp-per-voxel sparse conv, 4-entry batched, list-prefetched.
//  COUT==32: lane = oc, full CIN per lane (uniform gathers).
//  COUT==8 : lane -> (oc=lane&7, Cin slice lane>>3), shfl_xor reduce.
// Weights in SMEM [27][COUT][R], R = CIN+4 (16B-aligned rows).
// EPI: 0 none; 1: out = xres - conv (8ch); 2: out = tile(xres) + conv (32ch).
// ---------------------------------------------------------------------------
template <int CIN, int COUT, int EPI, int TB, int MINB>
__global__ void __launch_bounds__(TB, MINB)
conv_kernel(const float* __restrict__ in,
            const float* __restrict__ W,
            const float* __restrict__ xres,
            float* __restrict__ out, int N) {
    constexpr int csn = (COUT == 32) ? CIN : (CIN / 4);
    constexpr int CH  = (csn < 8) ? csn : 8;     // floats per lane per chunk
    constexpr int NCH = csn / CH;
    constexpr int R   = CIN + 4;
    extern __shared__ float Ws[];  // [27][COUT][R]

    const int tid = threadIdx.x;
    for (int i = tid; i < 27 * CIN * COUT; i += blockDim.x) {
        int k = i / (CIN * COUT);
        int rem = i % (CIN * COUT);
        int c = rem / COUT, j = rem % COUT;
        Ws[(k * COUT + j) * R + c] = W[i];
    }
    __syncthreads();

    const int lane = tid & 31;
    const int warp = tid >> 5;
    const int wpb  = blockDim.x >> 5;

    int oc, cs0;
    if (COUT == 32) { oc = lane; cs0 = 0; }
    else            { oc = lane & 7; cs0 = (lane >> 3) * csn; }

    const int gstride = gridDim.x * wpb;
    int n = blockIdx.x * wpb + warp;

    int4 Lc = (n < N)
            ? *reinterpret_cast<const int4*>(&g_list[(size_t)n * LSTR])
            : make_int4(0, 0, 0, 0);

    while (n < N) {
        const int nn = n + gstride;
        int4 Ln = (nn < N)
                ? *reinterpret_cast<const int4*>(&g_list[(size_t)nn * LSTR])
                : make_int4(0, 0, 0, 0);

        const int cnt = ((unsigned)Lc.x) >> 27;
        int ents[4];
        ents[0] = (13 << 20) | n;          // center tap, always active
        ents[1] = Lc.x & 0x07FFFFFF;
        ents[2] = Lc.y;
        ents[3] = Lc.z;

        float acc0 = 0.f, acc1 = 0.f, acc2 = 0.f, acc3 = 0.f;

#pragma unroll
        for (int ch = 0; ch < NCH; ch++) {
            float gb[4][CH];
            // --- batched predicated gather loads (back-to-back LDGs) ---
#pragma unroll
            for (int e = 0; e < 4; e++) {
                const bool act = e <= cnt;
                const float* p = in + (size_t)(ents[e] & 0xFFFFF) * CIN
                                    + cs0 + ch * CH;
                if constexpr ((CH & 3) == 0) {
#pragma unroll
                    for (int c = 0; c < CH; c += 4) {
                        float4 g = act ? *reinterpret_cast<const float4*>(p + c)
                                       : make_float4(0.f, 0.f, 0.f, 0.f);
                        gb[e][c] = g.x; gb[e][c + 1] = g.y;
                        gb[e][c + 2] = g.z; gb[e][c + 3] = g.w;
                    }
                } else {
                    float2 g = act ? *reinterpret_cast<const float2*>(p)
                                   : make_float2(0.f, 0.f);
                    gb[e][0] = g.x; gb[e][1] = g.y;
                }
            }
            // --- FMA, gated by warp-uniform cnt branches ---
            auto fma_e = [&](int e) {
                const int k = (ents[e] >> 20) & 31;
                const float* wr = &Ws[(k * COUT + oc) * R + cs0 + ch * CH];
                if constexpr ((CH & 3) == 0) {
#pragma unroll
                    for (int c = 0; c < CH; c += 4) {
                        float4 w = *reinterpret_cast<const float4*>(wr + c);
                        acc0 += gb[e][c]     * w.x;
                        acc1 += gb[e][c + 1] * w.y;
                        acc2 += gb[e][c + 2] * w.z;
                        acc3 += gb[e][c + 3] * w.w;
                    }
                } else {
                    float2 w = *reinterpret_cast<const float2*>(wr);
                    acc0 += gb[e][0] * w.x;
                    acc1 += gb[e][1] * w.y;
                }
            };
            fma_e(0);
            if (cnt >= 1) fma_e(1);
            if (cnt >= 2) { fma_e(2); fma_e(3); }
        }

        // --- rare tail: list entries beyond the first 3 (P ~ 6%) ---
#pragma unroll 1
        for (int i = 3; i < cnt; i++) {
            const int e   = g_list[(size_t)n * LSTR + i];
            const int k   = (e >> 20) & 31;
            const int src = e & 0xFFFFF;
            const float* p  = in + (size_t)src * CIN + cs0;
            const float* wr = &Ws[(k * COUT + oc) * R + cs0];
#pragma unroll
            for (int c = 0; c < csn; c++) acc0 += p[c] * wr[c];
        }

        float acc = (acc0 + acc1) + (acc2 + acc3);

        if constexpr (COUT == 8) {
            acc += __shfl_xor_sync(0xffffffffu, acc, 8);
            acc += __shfl_xor_sync(0xffffffffu, acc, 16);
            if (lane < 8) {
                float v = acc;
                if constexpr (EPI == 1) v = xres[(size_t)n * 8 + lane] - v;
                out[(size_t)n * 8 + lane] = v;
            }
        } else {
            float v = acc;
            if constexpr (EPI == 2) v += xres[(size_t)n * 8 + (lane & 7)];
            out[(size_t)n * 32 + lane] = v;
        }

        n = nn;
        Lc = Ln;
    }
}

// ---------------------------------------------------------------------------
extern "C" void kernel_launch(void* const* d_in, const int* in_sizes, int n_in,
                              void* d_out, int out_size) {
    const float* x    = (const float*)d_in[0];
    const int*   nbr  = (const int*)d_in[1];
    const void*  mask = (const void*)d_in[2];
    const float* Wd0  = (const float*)d_in[3];
    const float* Wd1  = (const float*)d_in[4];
    const float* Wd2  = (const float*)d_in[5];
    const float* Wu0  = (const float*)d_in[6];
    const float* Wu1  = (const float*)d_in[7];
    const float* Wu2  = (const float*)d_in[8];
    float*       out  = (float*)d_out;
    const int N = in_sizes[0] / 8;

    float *t32, *t8a, *t8b, *wfold;
    cudaGetSymbolAddress((void**)&t32,   g_t32);
    cudaGetSymbolAddress((void**)&t8a,   g_t8a);
    cudaGetSymbolAddress((void**)&t8b,   g_t8b);
    cudaGetSymbolAddress((void**)&wfold, g_wfold);

    const int smem_8_32  = 27 * 32 * 12 * 4;   //  41,472 B
    const int smem_32_8  = 27 * 8  * 36 * 4;   //  31,104 B
    const int smem_8_8   = 27 * 8  * 12 * 4;   //  10,368 B
    const int smem_32_32 = 27 * 32 * 36 * 4;   // 124,416 B

    cudaFuncSetAttribute((const void*)conv_kernel<32, 32, 2, 768, 1>,
                         cudaFuncAttributeMaxDynamicSharedMemorySize,
                         smem_32_32);

    detect_mask<<<1, 256>>>((const unsigned int*)mask);
    build_compact<<<(N + 255) / 256, 256>>>(nbr, mask, N);
    fold_wd0<<<(27 * 8 * 32 + 255) / 256, 256>>>(Wd0);

    // K1: conv(tile(x), Wd0) == conv(x, wfold)   8 -> 32
    conv_kernel<8, 32, 0, 256, 3><<<NSM * 3, 256, smem_8_32>>>(x, wfold, x, t32, N);
    // K2: 32 -> 8
    conv_kernel<32, 8, 0, 256, 3><<<NSM * 3, 256, smem_32_8>>>(t32, Wd1, x, t8a, N);
    // K3: 8 -> 8, epilogue r0 = x - d
    conv_kernel<8, 8, 1, 256, 6><<<NSM * 6, 256, smem_8_8>>>(t8a, Wd2, x, t8b, N);
    // K4: 8 -> 8
    conv_kernel<8, 8, 0, 256, 6><<<NSM * 6, 256, smem_8_8>>>(t8b, Wu0, x, t8a, N);
    // K5: 8 -> 32
    conv_kernel<8, 32, 0, 256, 3><<<NSM * 3, 256, smem_8_32>>>(t8a, Wu1, x, t32, N);
    // K6: 32 -> 32, epilogue out = tile(x) + conv   (124 KB smem -> 1 CTA/SM)
    conv_kernel<32, 32, 2, 768, 1><<<NSM, 768, smem_32_32>>>(t32, Wu2, x, out, N);
}

// round 7
// speedup vs baseline: 1.1734x; 1.1734x over previous
#include <cuda_runtime.h>
#include <cuda_bf16.h>
#include <cstdint>

// ---------------------------------------------------------------------------
// Sparse 3x3x3 conv chain, N=1e6 voxels. R7 = R5 structure (best) + bf16
// packed weights in SMEM (halves the binding L1/LDS crossbar traffic).
//  * per-voxel packed lists, cnt in entry0 bits[27:32), speculative int4 load
//  * ILP=2 voxels per warp iteration
//  * center tap (k=13) densified with fp32 register weights
//  * weights: bf16x2 rows, pitch 12/20 u32 (48/80B -> conflict-free LDS.128)
// ---------------------------------------------------------------------------

#define MAXN 1000000
#define NSM  148
#define LSTR 28   // per-voxel list stride (ints), 112B -> int4-aligned

__device__ int      g_mtype;               // 0=int32, 1=uint8, 2=float32
__device__ int      g_list[(size_t)MAXN * LSTR];
__device__ float    g_t32[(size_t)MAXN * 32];
__device__ float    g_t8a[(size_t)MAXN * 8];
__device__ float    g_t8b[(size_t)MAXN * 8];
__device__ float    g_wfold[27 * 8 * 32];
// packed bf16x2 weights, one region per conv (offsets below)
__device__ unsigned g_wpack[10368 + 4320 + 2592 + 2592 + 10368 + 17280];

#define WP0 0                        // <8,32>  pitch 12 : 27*32*12 = 10368
#define WP1 (WP0 + 10368)            // <32,8>  pitch 20 : 27*8*20  =  4320
#define WP2 (WP1 + 4320)             // <8,8>   pitch 12 : 27*8*12  =  2592
#define WP3 (WP2 + 2592)
#define WP4 (WP3 + 2592)             // <8,32>
#define WP5 (WP4 + 10368)            // <32,32> pitch 20 : 27*32*20 = 17280

// ---------------------------------------------------------------------------
__global__ void detect_mask(const unsigned int* __restrict__ m) {
    __shared__ int s_u8, s_f32;
    if (threadIdx.x == 0) { s_u8 = 0; s_f32 = 0; }
    __syncthreads();
    int loc_u8 = 0, loc_f32 = 0;
    for (int i = threadIdx.x; i < 65536; i += blockDim.x) {
        unsigned v = m[i];
        if (v == 0x3F800000u) loc_f32 = 1;
        else if (v > 1u)      loc_u8 = 1;
    }
    if (loc_u8)  atomicOr(&s_u8, 1);
    if (loc_f32) atomicOr(&s_f32, 1);
    __syncthreads();
    if (threadIdx.x == 0) g_mtype = s_f32 ? 2 : (s_u8 ? 1 : 0);
}

// Off-center entries only (k==13 densified). entry=(k<<20)|src; entry0 also
// carries cnt in bits [27:32).
__global__ void build_compact(const int* __restrict__ nbr,
                              const void* __restrict__ maskv, int N) {
    int n = blockIdx.x * blockDim.x + threadIdx.x;
    if (n >= N) return;
    const int mt = g_mtype;
    const int*           mi = (const int*)maskv;
    const unsigned char* mb = (const unsigned char*)maskv;
    const float*         mf = (const float*)maskv;
    int cnt = 0, first = 0;
    int* lst = &g_list[(size_t)n * LSTR];
#pragma unroll 1
    for (int k = 0; k < 27; k++) {
        if (k == 13) continue;
        size_t o = (size_t)k * N + n;
        bool on;
        if (mt == 0)      on = mi[o] != 0;
        else if (mt == 1) on = mb[o] != 0;
        else              on = mf[o] != 0.0f;
        if (on) {
            int e = (k << 20) | nbr[o];
            if (cnt == 0) first = e;
            else          lst[cnt] = e;
            cnt++;
        }
    }
    lst[0] = first | (cnt << 27);
    if (cnt < 2) lst[1] = 0;
    if (cnt < 3) lst[2] = 0;
    if (cnt < 4) lst[3] = 0;
}

// Fold tile(x,(1,4)) into Wd0: wfold[k][c][j] = sum_t Wd0[k][c+8t][j]
__global__ void fold_wd0(const float* __restrict__ Wd0) {
    int i = blockIdx.x * blockDim.x + threadIdx.x;
    if (i >= 27 * 8 * 32) return;
    int k = i / 256, rem = i % 256;
    int c = rem / 32, j = rem % 32;
    float s = 0.f;
#pragma unroll
    for (int t = 0; t < 4; t++) s += Wd0[k * 1024 + (c + 8 * t) * 32 + j];
    g_wfold[i] = s;
}

// Pack W[k][c][oc] (fp32) -> bf16x2 rows [k][oc][c/2] with pitch PITCH u32.
__global__ void pack_w(const float* __restrict__ W, unsigned* __restrict__ dst,
                       int CIN, int COUT, int PITCH) {
    int i = blockIdx.x * blockDim.x + threadIdx.x;
    int c2n = CIN >> 1;
    int total = 27 * COUT * c2n;
    if (i >= total) return;
    int c2 = i % c2n;
    int rest = i / c2n;
    int oc = rest % COUT, k = rest / COUT;
    float a = W[(k * CIN + 2 * c2)     * COUT + oc];
    float b = W[(k * CIN + 2 * c2 + 1) * COUT + oc];
    __nv_bfloat162 p = __floats2bfloat162_rn(a, b);
    dst[(k * COUT + oc) * PITCH + c2] = *reinterpret_cast<unsigned*>(&p);
}

// exact bf16x2 -> float2 expansion (2 ALU ops, no F2F pipe)
__device__ __forceinline__ float2 bf2f(unsigned u) {
    float2 r;
    r.x = __uint_as_float(u << 16);
    r.y = __uint_as_float(u & 0xFFFF0000u);
    return r;
}

// ---------------------------------------------------------------------------
// Warp-per-voxel (x ILP) sparse conv, dense fp32 center tap, bf16 weights.
//  COUT==32: lane = oc, full CIN per lane.
//  COUT==8 : lane -> (oc=lane&7, Cin slice lane>>3), shfl_xor reduce.
// EPI: 0 none; 1: out = xres - conv (8ch); 2: out = tile(xres) + conv (32ch).
// ---------------------------------------------------------------------------
template <int CIN, int COUT, int EPI, int TB, int MINB, int ILP>
__global__ void __launch_bounds__(TB, MINB)
conv_kernel(const float* __restrict__ in,
            const unsigned* __restrict__ WP,   // packed bf16x2 weights
            const float* __restrict__ Wf,      // fp32 weights (center tap)
            const float* __restrict__ xres,
            float* __restrict__ out, int N) {
    constexpr int csn   = (COUT == 32) ? CIN : (CIN / 4);
    constexpr int PITCH = (CIN == 8) ? 12 : 20;   // u32; 48B / 80B rows
    extern __shared__ unsigned Ws[];              // [27][COUT][PITCH]

    const int tid = threadIdx.x;
    for (int i = tid; i < 27 * COUT * PITCH; i += blockDim.x)
        Ws[i] = WP[i];
    __syncthreads();

    const int lane = tid & 31;
    const int warp = tid >> 5;
    const int wpb  = blockDim.x >> 5;

    int oc, cs0;
    if (COUT == 32) { oc = lane; cs0 = 0; }
    else            { oc = lane & 7; cs0 = (lane >> 3) * csn; }

    // center-tap weights fp32 in registers
    float wc[csn];
#pragma unroll
    for (int c = 0; c < csn; c++)
        wc[c] = Wf[(13 * CIN + cs0 + c) * COUT + oc];

    const int gw      = blockIdx.x * wpb + warp;
    const int gstride = gridDim.x * wpb;

    for (int base = gw * ILP; base < N; base += gstride * ILP) {
        int4 L[ILP];
#pragma unroll
        for (int j = 0; j < ILP; j++) {
            int n = base + j;
            L[j] = (n < N)
                 ? *reinterpret_cast<const int4*>(&g_list[(size_t)n * LSTR])
                 : make_int4(0, 0, 0, 0);
        }
#pragma unroll
        for (int j = 0; j < ILP; j++) {
            const int n = base + j;
            if (n >= N) break;
            const int cnt = ((unsigned)L[j].x) >> 27;
            const float* xr = &in[(size_t)n * CIN];
            float acc0 = 0.f, acc1 = 0.f, acc2 = 0.f, acc3 = 0.f;

            // ---- dense center tap (fp32 register weights) ----
            if constexpr ((csn & 3) == 0) {
                const float4* x4 = reinterpret_cast<const float4*>(xr + cs0);
#pragma unroll
                for (int c = 0; c < csn / 4; c++) {
                    float4 g = x4[c];
                    acc0 += g.x * wc[4 * c + 0];
                    acc1 += g.y * wc[4 * c + 1];
                    acc2 += g.z * wc[4 * c + 2];
                    acc3 += g.w * wc[4 * c + 3];
                }
            } else {
#pragma unroll
                for (int c = 0; c < csn; c++) acc0 += xr[cs0 + c] * wc[c];
            }

            // ---- off-center entries: bf16 weights from SMEM ----
            auto do_entry = [&](int e) {
                const int k   = (e >> 20) & 31;
                const int src = e & 0xFFFFF;
                const float* grow = &in[(size_t)src * CIN + cs0];
                const unsigned* wrow = &Ws[(k * COUT + oc) * PITCH + (cs0 >> 1)];
                if constexpr (csn >= 8) {
                    const float4* g4 = reinterpret_cast<const float4*>(grow);
                    const uint4*  w4 = reinterpret_cast<const uint4*>(wrow);
#pragma unroll
                    for (int b = 0; b < csn / 8; b++) {
                        float4 ga = g4[2 * b], gb = g4[2 * b + 1];
                        uint4 w = w4[b];
                        float2 w0 = bf2f(w.x), w1 = bf2f(w.y);
                        float2 w2 = bf2f(w.z), w3 = bf2f(w.w);
                        acc0 += ga.x * w0.x; acc1 += ga.y * w0.y;
                        acc2 += ga.z * w1.x; acc3 += ga.w * w1.y;
                        acc0 += gb.x * w2.x; acc1 += gb.y * w2.y;
                        acc2 += gb.z * w3.x; acc3 += gb.w * w3.y;
                    }
                } else {  // csn == 2
                    float2 g = *reinterpret_cast<const float2*>(grow);
                    float2 w = bf2f(wrow[0]);
                    acc0 += g.x * w.x;
                    acc1 += g.y * w.y;
                }
            };

            if (cnt > 0) do_entry(L[j].x & 0x07FFFFFF);
            if (cnt > 1) do_entry(L[j].y);
            if (cnt > 2) do_entry(L[j].z);
            if (cnt > 3) do_entry(L[j].w);
#pragma unroll 1
            for (int i = 4; i < cnt; i++)
                do_entry(g_list[(size_t)n * LSTR + i]);

            float acc = (acc0 + acc1) + (acc2 + acc3);

            if constexpr (COUT == 8) {
                acc += __shfl_xor_sync(0xffffffffu, acc, 8);
                acc += __shfl_xor_sync(0xffffffffu, acc, 16);
                if (lane < 8) {
                    float v = acc;
                    if constexpr (EPI == 1) v = xres[(size_t)n * 8 + lane] - v;
                    out[(size_t)n * 8 + lane] = v;
                }
            } else {
                float v = acc;
                if constexpr (EPI == 2) v += xres[(size_t)n * 8 + (lane & 7)];
                out[(size_t)n * 32 + lane] = v;
            }
        }
    }
}

// ---------------------------------------------------------------------------
extern "C" void kernel_launch(void* const* d_in, const int* in_sizes, int n_in,
                              void* d_out, int out_size) {
    const float* x    = (const float*)d_in[0];
    const int*   nbr  = (const int*)d_in[1];
    const void*  mask = (const void*)d_in[2];
    const float* Wd1  = (const float*)d_in[4];
    const float* Wd2  = (const float*)d_in[5];
    const float* Wu0  = (const float*)d_in[6];
    const float* Wu1  = (const float*)d_in[7];
    const float* Wu2  = (const float*)d_in[8];
    const float* Wd0  = (const float*)d_in[3];
    float*       out  = (float*)d_out;
    const int N = in_sizes[0] / 8;

    float *t32, *t8a, *t8b, *wfold;
    unsigned* wp;
    cudaGetSymbolAddress((void**)&t32,   g_t32);
    cudaGetSymbolAddress((void**)&t8a,   g_t8a);
    cudaGetSymbolAddress((void**)&t8b,   g_t8b);
    cudaGetSymbolAddress((void**)&wfold, g_wfold);
    cudaGetSymbolAddress((void**)&wp,    g_wpack);

    const int smem_8_32  = 27 * 32 * 12 * 4;   // 41,472 B
    const int smem_32_8  = 27 * 8  * 20 * 4;   //  8,640 B
    const int smem_8_8   = 27 * 8  * 12 * 4;   //  5,184 B
    const int smem_32_32 = 27 * 32 * 20 * 4;   // 69,120 B

    cudaFuncSetAttribute((const void*)conv_kernel<32, 32, 2, 512, 2, 1>,
                         cudaFuncAttributeMaxDynamicSharedMemorySize,
                         smem_32_32);

    detect_mask<<<1, 256>>>((const unsigned int*)mask);
    build_compact<<<(N + 255) / 256, 256>>>(nbr, mask, N);
    fold_wd0<<<(27 * 8 * 32 + 255) / 256, 256>>>(Wd0);

    pack_w<<<(27 * 32 * 4  + 255) / 256, 256>>>(wfold, wp + WP0,  8, 32, 12);
    pack_w<<<(27 * 8  * 16 + 255) / 256, 256>>>(Wd1,   wp + WP1, 32,  8, 20);
    pack_w<<<(27 * 8  * 4  + 255) / 256, 256>>>(Wd2,   wp + WP2,  8,  8, 12);
    pack_w<<<(27 * 8  * 4  + 255) / 256, 256>>>(Wu0,   wp + WP3,  8,  8, 12);
    pack_w<<<(27 * 32 * 4  + 255) / 256, 256>>>(Wu1,   wp + WP4,  8, 32, 12);
    pack_w<<<(27 * 32 * 16 + 255) / 256, 256>>>(Wu2,   wp + WP5, 32, 32, 20);

    // K1: conv(tile(x), Wd0) == conv(x, wfold)   8 -> 32
    conv_kernel<8, 32, 0, 256, 5, 2><<<NSM * 5, 256, smem_8_32>>>(x, wp + WP0, wfold, x, t32, N);
    // K2: 32 -> 8
    conv_kernel<32, 8, 0, 256, 6, 2><<<NSM * 6, 256, smem_32_8>>>(t32, wp + WP1, Wd1, x, t8a, N);
    // K3: 8 -> 8, epilogue r0 = x - d
    conv_kernel<8, 8, 1, 256, 8, 2><<<NSM * 8, 256, smem_8_8>>>(t8a, wp + WP2, Wd2, x, t8b, N);
    // K4: 8 -> 8
    conv_kernel<8, 8, 0, 256, 8, 2><<<NSM * 8, 256, smem_8_8>>>(t8b, wp + WP3, Wu0, x, t8a, N);
    // K5: 8 -> 32
    conv_kernel<8, 32, 0, 256, 5, 2><<<NSM * 5, 256, smem_8_32>>>(t8a, wp + WP4, Wu1, x, t32, N);
    // K6: 32 -> 32, epilogue out = tile(x) + conv   (69 KB smem -> 2 CTA/SM)
    conv_kernel<32, 32, 2, 512, 2, 1><<<NSM * 2, 512, smem_32_32>>>(t32, wp + WP5, Wu2, x, out, N);
}

// round 9
// speedup vs baseline: 1.4332x; 1.2214x over previous
#include <cuda_runtime.h>
#include <cuda_bf16.h>
#include <cstdint>

// ---------------------------------------------------------------------------
// Sparse 3x3x3 conv chain, N=1e6 voxels. R8:
//  * bf16 intermediate activations (t32: 64MB, t8: 16MB -> L2-resident,
//    gathers halve; K2 slice = single LDG.128)
//  * compact stride-8 list (32MB, L2-resident) + rare overflow tier
//  * all weights bf16x2 in SMEM (center tap incl. -> fewer regs)
//  * R5 loop shape: speculative int4 list load, ILP=2, gated entry FMAs
// ---------------------------------------------------------------------------

#define MAXN 1000000
#define NSM  148
#define LOV  20

__device__ int      g_mtype;               // 0=int32, 1=uint8, 2=float32
__device__ int      g_l8[(size_t)MAXN * 8];    // entries 0..7 (e0 carries cnt)
__device__ int      g_lov[(size_t)MAXN * LOV]; // entries 8.. (cnt>8, rare)
__device__ unsigned g_t32p[(size_t)MAXN * 16]; // bf16x2 activations, 32 ch
__device__ unsigned g_t8ap[(size_t)MAXN * 4];  // bf16x2 activations, 8 ch
__device__ unsigned g_t8bp[(size_t)MAXN * 4];
__device__ float    g_wfold[27 * 8 * 32];
__device__ unsigned g_wpack[6912 + 4320 + 1728 + 1728 + 6912 + 17280];

#define WQ0 0                  // K1 <8,32>  pitch 8  : 6912
#define WQ1 (WQ0 + 6912)       // K2 <32,8>  pitch 20 : 4320
#define WQ2 (WQ1 + 4320)       // K3 <8,8>   pitch 8  : 1728
#define WQ3 (WQ2 + 1728)       // K4 <8,8>
#define WQ4 (WQ3 + 1728)       // K5 <8,32>
#define WQ5 (WQ4 + 6912)       // K6 <32,32> pitch 20 : 17280

// ---------------------------------------------------------------------------
__global__ void detect_mask(const unsigned int* __restrict__ m) {
    __shared__ int s_u8, s_f32;
    if (threadIdx.x == 0) { s_u8 = 0; s_f32 = 0; }
    __syncthreads();
    int loc_u8 = 0, loc_f32 = 0;
    for (int i = threadIdx.x; i < 65536; i += blockDim.x) {
        unsigned v = m[i];
        if (v == 0x3F800000u) loc_f32 = 1;
        else if (v > 1u)      loc_u8 = 1;
    }
    if (loc_u8)  atomicOr(&s_u8, 1);
    if (loc_f32) atomicOr(&s_f32, 1);
    __syncthreads();
    if (threadIdx.x == 0) g_mtype = s_f32 ? 2 : (s_u8 ? 1 : 0);
}

// Off-center entries (k==13 is synthetic entry0 in conv). entry=(k<<20)|src;
// slot0 also carries cnt in bits [27:32). Entries 8.. go to overflow tier.
__global__ void build_compact(const int* __restrict__ nbr,
                              const void* __restrict__ maskv, int N) {
    int n = blockIdx.x * blockDim.x + threadIdx.x;
    if (n >= N) return;
    const int mt = g_mtype;
    const int*           mi = (const int*)maskv;
    const unsigned char* mb = (const unsigned char*)maskv;
    const float*         mf = (const float*)maskv;
    int cnt = 0, first = 0;
    int* lst = &g_l8[(size_t)n * 8];
#pragma unroll 1
    for (int k = 0; k < 27; k++) {
        if (k == 13) continue;
        size_t o = (size_t)k * N + n;
        bool on;
        if (mt == 0)      on = mi[o] != 0;
        else if (mt == 1) on = mb[o] != 0;
        else              on = mf[o] != 0.0f;
        if (on) {
            int e = (k << 20) | nbr[o];
            if (cnt == 0)      first = e;
            else if (cnt < 8)  lst[cnt] = e;
            else               g_lov[(size_t)n * LOV + cnt - 8] = e;
            cnt++;
        }
    }
    lst[0] = first | (cnt << 27);
    if (cnt < 2) lst[1] = 0;
    if (cnt < 3) lst[2] = 0;
    if (cnt < 4) lst[3] = 0;
}

// Fold tile(x,(1,4)) into Wd0: wfold[k][c][j] = sum_t Wd0[k][c+8t][j]
__global__ void fold_wd0(const float* __restrict__ Wd0) {
    int i = blockIdx.x * blockDim.x + threadIdx.x;
    if (i >= 27 * 8 * 32) return;
    int k = i / 256, rem = i % 256;
    int c = rem / 32, j = rem % 32;
    float s = 0.f;
#pragma unroll
    for (int t = 0; t < 4; t++) s += Wd0[k * 1024 + (c + 8 * t) * 32 + j];
    g_wfold[i] = s;
}

// Pack W[k][c][oc] fp32 -> bf16x2 rows [k][oc][c/2], pitch PITCH u32.
__global__ void pack_w(const float* __restrict__ W, unsigned* __restrict__ dst,
                       int CIN, int COUT, int PITCH) {
    int i = blockIdx.x * blockDim.x + threadIdx.x;
    int c2n = CIN >> 1;
    int total = 27 * COUT * c2n;
    if (i >= total) return;
    int c2 = i % c2n;
    int rest = i / c2n;
    int oc = rest % COUT, k = rest / COUT;
    float a = W[(k * CIN + 2 * c2)     * COUT + oc];
    float b = W[(k * CIN + 2 * c2 + 1) * COUT + oc];
    __nv_bfloat16 lb = __float2bfloat16(a), hb = __float2bfloat16(b);
    unsigned ls = *reinterpret_cast<unsigned short*>(&lb);
    unsigned hs = *reinterpret_cast<unsigned short*>(&hb);
    dst[(k * COUT + oc) * PITCH + c2] = ls | (hs << 16);
}

// exact bf16x2 -> float2 (2 ALU ops)
__device__ __forceinline__ float2 bf2f(unsigned u) {
    float2 r;
    r.x = __uint_as_float(u << 16);
    r.y = __uint_as_float(u & 0xFFFF0000u);
    return r;
}
__device__ __forceinline__ unsigned f2b2(float lo, float hi) {
    __nv_bfloat16 l = __float2bfloat16(lo), h = __float2bfloat16(hi);
    unsigned ls = *reinterpret_cast<unsigned short*>(&l);
    unsigned hs = *reinterpret_cast<unsigned short*>(&h);
    return ls | (hs << 16);
}

// ---------------------------------------------------------------------------
// Warp-per-voxel (x ILP) sparse conv. Center tap = synthetic entry (k=13).
//  COUT==32: lane = oc, full CIN per lane.
//  COUT==8 : lane -> (oc=lane&7, Cin slice lane>>3), shfl_xor reduce.
// Weights bf16x2 in SMEM [27][COUT][PITCH]; activations bf16x2 when INBF.
// EPI: 0 none; 1: out = xres - conv (8ch); 2: out = tile(xres) + conv (32ch).
// ---------------------------------------------------------------------------
template <int CIN, int COUT, int EPI, int TB, int MINB, int ILP,
          bool INBF, bool OUTBF>
__global__ void __launch_bounds__(TB, MINB)
conv_kernel(const void* __restrict__ in,
            const unsigned* __restrict__ WP,
            const float* __restrict__ xres,
            void* __restrict__ out, int N) {
    constexpr int csn   = (COUT == 32) ? CIN : (CIN / 4);
    constexpr int PITCH = (CIN == 8) ? 8 : 20;
    extern __shared__ unsigned Ws[];  // [27][COUT][PITCH]

    const int tid = threadIdx.x;
    for (int i = tid; i < 27 * COUT * PITCH; i += blockDim.x)
        Ws[i] = WP[i];
    __syncthreads();

    const int lane = tid & 31;
    const int warp = tid >> 5;
    const int wpb  = blockDim.x >> 5;

    int oc, cs0;
    if (COUT == 32) { oc = lane; cs0 = 0; }
    else            { oc = lane & 7; cs0 = (lane >> 3) * csn; }

    const int gw      = blockIdx.x * wpb + warp;
    const int gstride = gridDim.x * wpb;

    for (int base = gw * ILP; base < N; base += gstride * ILP) {
        int4 L[ILP];
#pragma unroll
        for (int j = 0; j < ILP; j++) {
            int n = base + j;
            L[j] = (n < N)
                 ? *reinterpret_cast<const int4*>(&g_l8[(size_t)n * 8])
                 : make_int4(0, 0, 0, 0);
        }
#pragma unroll
        for (int j = 0; j < ILP; j++) {
            const int n = base + j;
            if (n >= N) break;
            const int cnt = ((unsigned)L[j].x) >> 27;
            float acc0 = 0.f, acc1 = 0.f, acc2 = 0.f, acc3 = 0.f;

            auto do_entry = [&](int e) {
                const int k   = (e >> 20) & 31;
                const int src = e & 0xFFFFF;
                const unsigned* wrow =
                    &Ws[(k * COUT + oc) * PITCH + (cs0 >> 1)];
                if constexpr (INBF) {
                    const unsigned* gp = (const unsigned*)in
                                       + (size_t)src * (CIN / 2) + (cs0 >> 1);
                    if constexpr (csn == 2) {
                        float2 a = bf2f(gp[0]);
                        float2 w = bf2f(wrow[0]);
                        acc0 += a.x * w.x;
                        acc1 += a.y * w.y;
                    } else {
#pragma unroll
                        for (int b = 0; b < csn / 8; b++) {
                            uint4 gv = reinterpret_cast<const uint4*>(gp)[b];
                            uint4 wv = reinterpret_cast<const uint4*>(wrow)[b];
                            float2 a0 = bf2f(gv.x), a1 = bf2f(gv.y);
                            float2 a2 = bf2f(gv.z), a3 = bf2f(gv.w);
                            float2 w0 = bf2f(wv.x), w1 = bf2f(wv.y);
                            float2 w2 = bf2f(wv.z), w3 = bf2f(wv.w);
                            acc0 += a0.x * w0.x; acc1 += a0.y * w0.y;
                            acc2 += a1.x * w1.x; acc3 += a1.y * w1.y;
                            acc0 += a2.x * w2.x; acc1 += a2.y * w2.y;
                            acc2 += a3.x * w3.x; acc3 += a3.y * w3.y;
                        }
                    }
                } else {  // fp32 input (K1: csn==8)
                    const float* gp = (const float*)in
                                    + (size_t)src * CIN + cs0;
#pragma unroll
                    for (int b = 0; b < csn / 8; b++) {
                        float4 ga = reinterpret_cast<const float4*>(gp)[2 * b];
                        float4 gb = reinterpret_cast<const float4*>(gp)[2 * b + 1];
                        uint4 wv = reinterpret_cast<const uint4*>(wrow)[b];
                        float2 w0 = bf2f(wv.x), w1 = bf2f(wv.y);
                        float2 w2 = bf2f(wv.z), w3 = bf2f(wv.w);
                        acc0 += ga.x * w0.x; acc1 += ga.y * w0.y;
                        acc2 += ga.z * w1.x; acc3 += ga.w * w1.y;
                        acc0 += gb.x * w2.x; acc1 += gb.y * w2.y;
                        acc2 += gb.z * w3.x; acc3 += gb.w * w3.y;
                    }
                }
            };

            do_entry((13 << 20) | n);                 // center tap
            if (cnt > 0) do_entry(L[j].x & 0x07FFFFFF);
            if (cnt > 1) do_entry(L[j].y);
            if (cnt > 2) do_entry(L[j].z);
            if (cnt > 3) do_entry(L[j].w);
            if (cnt > 4) {
                int4 M = *reinterpret_cast<const int4*>(&g_l8[(size_t)n * 8 + 4]);
                do_entry(M.x);
                if (cnt > 5) do_entry(M.y);
                if (cnt > 6) do_entry(M.z);
                if (cnt > 7) do_entry(M.w);
#pragma unroll 1
                for (int i = 8; i < cnt; i++)
                    do_entry(g_lov[(size_t)n * LOV + i - 8]);
            }

            float acc = (acc0 + acc1) + (acc2 + acc3);

            if constexpr (COUT == 8) {
                acc += __shfl_xor_sync(0xffffffffu, acc, 8);
                acc += __shfl_xor_sync(0xffffffffu, acc, 16);
                float v = acc;
                if constexpr (EPI == 1)
                    v = xres[(size_t)n * 8 + (lane & 7)] - v;
                if constexpr (OUTBF) {
                    float pv = __shfl_xor_sync(0xffffffffu, v, 1);
                    if (lane < 8 && (lane & 1) == 0)
                        ((unsigned*)out)[(size_t)n * 4 + (lane >> 1)] = f2b2(v, pv);
                } else {
                    if (lane < 8)
                        ((float*)out)[(size_t)n * 8 + lane] = v;
                }
            } else {
                float v = acc;
                if constexpr (EPI == 2)
                    v += xres[(size_t)n * 8 + (lane & 7)];
                if constexpr (OUTBF) {
                    float pv = __shfl_xor_sync(0xffffffffu, v, 1);
                    if ((lane & 1) == 0)
                        ((unsigned*)out)[(size_t)n * 16 + (lane >> 1)] = f2b2(v, pv);
                } else {
                    ((float*)out)[(size_t)n * 32 + lane] = v;
                }
            }
        }
    }
}

// ---------------------------------------------------------------------------
extern "C" void kernel_launch(void* const* d_in, const int* in_sizes, int n_in,
                              void* d_out, int out_size) {
    const float* x    = (const float*)d_in[0];
    const int*   nbr  = (const int*)d_in[1];
    const void*  mask = (const void*)d_in[2];
    const float* Wd0  = (const float*)d_in[3];
    const float* Wd1  = (const float*)d_in[4];
    const float* Wd2  = (const float*)d_in[5];
    const float* Wu0  = (const float*)d_in[6];
    const float* Wu1  = (const float*)d_in[7];
    const float* Wu2  = (const float*)d_in[8];
    float*       out  = (float*)d_out;
    const int N = in_sizes[0] / 8;

    unsigned *t32, *t8a, *t8b, *wp;
    float* wfold;
    cudaGetSymbolAddress((void**)&t32,   g_t32p);
    cudaGetSymbolAddress((void**)&t8a,   g_t8ap);
    cudaGetSymbolAddress((void**)&t8b,   g_t8bp);
    cudaGetSymbolAddress((void**)&wfold, g_wfold);
    cudaGetSymbolAddress((void**)&wp,    g_wpack);

    const int sm_8_32  = 6912  * 4;   // 27,648 B
    const int sm_32_8  = 4320  * 4;   // 17,280 B
    const int sm_8_8   = 1728  * 4;   //  6,912 B
    const int sm_32_32 = 17280 * 4;   // 69,120 B

    cudaFuncSetAttribute(
        (const void*)conv_kernel<32, 32, 2, 512, 2, 1, true, false>,
        cudaFuncAttributeMaxDynamicSharedMemorySize, sm_32_32);

    detect_mask<<<1, 256>>>((const unsigned int*)mask);
    build_compact<<<(N + 255) / 256, 256>>>(nbr, mask, N);
    fold_wd0<<<(27 * 8 * 32 + 255) / 256, 256>>>(Wd0);

    pack_w<<<(27 * 32 * 4  + 255) / 256, 256>>>(wfold, wp + WQ0,  8, 32,  8);
    pack_w<<<(27 * 8  * 16 + 255) / 256, 256>>>(Wd1,   wp + WQ1, 32,  8, 20);
    pack_w<<<(27 * 8  * 4  + 255) / 256, 256>>>(Wd2,   wp + WQ2,  8,  8,  8);
    pack_w<<<(27 * 8  * 4  + 255) / 256, 256>>>(Wu0,   wp + WQ3,  8,  8,  8);
    pack_w<<<(27 * 32 * 4  + 255) / 256, 256>>>(Wu1,   wp + WQ4,  8, 32,  8);
    pack_w<<<(27 * 32 * 16 + 255) / 256, 256>>>(Wu2,   wp + WQ5, 32, 32, 20);

    // K1: 8 -> 32 (fp32 x in, bf16 t32 out), tile folded into weights
    conv_kernel<8, 32, 0, 256, 6, 2, false, true>
        <<<NSM * 6, 256, sm_8_32>>>(x, wp + WQ0, x, t32, N);
    // K2: 32 -> 8 (bf16 in/out)
    conv_kernel<32, 8, 0, 256, 6, 2, true, true>
        <<<NSM * 6, 256, sm_32_8>>>(t32, wp + WQ1, x, t8a, N);
    // K3: 8 -> 8, epilogue r = x - d (bf16 in/out)
    conv_kernel<8, 8, 1, 256, 6, 2, true, true>
        <<<NSM * 6, 256, sm_8_8>>>(t8a, wp + WQ2, x, t8b, N);
    // K4: 8 -> 8 (bf16 in/out)
    conv_kernel<8, 8, 0, 256, 6, 2, true, true>
        <<<NSM * 6, 256, sm_8_8>>>(t8b, wp + WQ3, x, t8a, N);
    // K5: 8 -> 32 (bf16 in/out)
    conv_kernel<8, 32, 0, 256, 6, 2, true, true>
        <<<NSM * 6, 256, sm_8_32>>>(t8a, wp + WQ4, x, t32, N);
    // K6: 32 -> 32, epilogue out = tile(x) + conv (bf16 in, fp32 out)
    conv_kernel<32, 32, 2, 512, 2, 1, true, false>
        <<<NSM * 2, 512, sm_32_32>>>(t32, wp + WQ5, x, out, N);
}

// round 10
// speedup vs baseline: 1.6110x; 1.1241x over previous
#include <cuda_runtime.h>
#include <cuda_bf16.h>
#include <cstdint>

// ---------------------------------------------------------------------------
// Sparse 3x3x3 conv chain, N=1e6 voxels. R10 = R8 + packed bf16 HFMA2 math:
//  * activations AND weights bf16x2; inner product via __hfma2 (BF16_V2)
//    -> K6 per-entry issues 104 -> 24 (no scalar expansion ALU)
//  * x packed to bf16 once; all convs use the packed path
//  * fp32 only in epilogues (residual subtract / final add)
// ---------------------------------------------------------------------------

#define MAXN 1000000
#define NSM  148
#define LOV  20

__device__ int      g_mtype;               // 0=int32, 1=uint8, 2=float32
__device__ int      g_l8[(size_t)MAXN * 8];    // entries 0..7 (e0 carries cnt)
__device__ int      g_lov[(size_t)MAXN * LOV]; // entries 8.. (rare)
__device__ unsigned g_xbf[(size_t)MAXN * 4];   // x as bf16x2, 8 ch
__device__ unsigned g_t32p[(size_t)MAXN * 16]; // bf16x2, 32 ch
__device__ unsigned g_t8ap[(size_t)MAXN * 4];  // bf16x2, 8 ch
__device__ unsigned g_t8bp[(size_t)MAXN * 4];
__device__ float    g_wfold[27 * 8 * 32];
__device__ unsigned g_wpack[6912 + 4320 + 1728 + 1728 + 6912 + 17280];

#define WQ0 0                  // K1 <8,32>  pitch 8  : 6912
#define WQ1 (WQ0 + 6912)       // K2 <32,8>  pitch 20 : 4320
#define WQ2 (WQ1 + 4320)       // K3 <8,8>   pitch 8  : 1728
#define WQ3 (WQ2 + 1728)       // K4 <8,8>
#define WQ4 (WQ3 + 1728)       // K5 <8,32>
#define WQ5 (WQ4 + 6912)       // K6 <32,32> pitch 20 : 17280

// ---------------------------------------------------------------------------
__global__ void detect_mask(const unsigned int* __restrict__ m) {
    __shared__ int s_u8, s_f32;
    if (threadIdx.x == 0) { s_u8 = 0; s_f32 = 0; }
    __syncthreads();
    int loc_u8 = 0, loc_f32 = 0;
    for (int i = threadIdx.x; i < 65536; i += blockDim.x) {
        unsigned v = m[i];
        if (v == 0x3F800000u) loc_f32 = 1;
        else if (v > 1u)      loc_u8 = 1;
    }
    if (loc_u8)  atomicOr(&s_u8, 1);
    if (loc_f32) atomicOr(&s_f32, 1);
    __syncthreads();
    if (threadIdx.x == 0) g_mtype = s_f32 ? 2 : (s_u8 ? 1 : 0);
}

__global__ void build_compact(const int* __restrict__ nbr,
                              const void* __restrict__ maskv, int N) {
    int n = blockIdx.x * blockDim.x + threadIdx.x;
    if (n >= N) return;
    const int mt = g_mtype;
    const int*           mi = (const int*)maskv;
    const unsigned char* mb = (const unsigned char*)maskv;
    const float*         mf = (const float*)maskv;
    int cnt = 0, first = 0;
    int* lst = &g_l8[(size_t)n * 8];
#pragma unroll 1
    for (int k = 0; k < 27; k++) {
        if (k == 13) continue;
        size_t o = (size_t)k * N + n;
        bool on;
        if (mt == 0)      on = mi[o] != 0;
        else if (mt == 1) on = mb[o] != 0;
        else              on = mf[o] != 0.0f;
        if (on) {
            int e = (k << 20) | nbr[o];
            if (cnt == 0)      first = e;
            else if (cnt < 8)  lst[cnt] = e;
            else               g_lov[(size_t)n * LOV + cnt - 8] = e;
            cnt++;
        }
    }
    lst[0] = first | (cnt << 27);
    if (cnt < 2) lst[1] = 0;
    if (cnt < 3) lst[2] = 0;
    if (cnt < 4) lst[3] = 0;
}

// Fold tile(x,(1,4)) into Wd0: wfold[k][c][j] = sum_t Wd0[k][c+8t][j]
__global__ void fold_wd0(const float* __restrict__ Wd0) {
    int i = blockIdx.x * blockDim.x + threadIdx.x;
    if (i >= 27 * 8 * 32) return;
    int k = i / 256, rem = i % 256;
    int c = rem / 32, j = rem % 32;
    float s = 0.f;
#pragma unroll
    for (int t = 0; t < 4; t++) s += Wd0[k * 1024 + (c + 8 * t) * 32 + j];
    g_wfold[i] = s;
}

__device__ __forceinline__ unsigned f2b2(float lo, float hi) {
    __nv_bfloat162 p = __floats2bfloat162_rn(lo, hi);
    return *reinterpret_cast<unsigned*>(&p);
}
__device__ __forceinline__ float2 bf2f(unsigned u) {
    float2 r;
    r.x = __uint_as_float(u << 16);
    r.y = __uint_as_float(u & 0xFFFF0000u);
    return r;
}
__device__ __forceinline__ __nv_bfloat162 u2b(unsigned u) {
    return *reinterpret_cast<__nv_bfloat162*>(&u);
}

// Pack W[k][c][oc] fp32 -> bf16x2 rows [k][oc][c/2], pitch PITCH u32.
__global__ void pack_w(const float* __restrict__ W, unsigned* __restrict__ dst,
                       int CIN, int COUT, int PITCH) {
    int i = blockIdx.x * blockDim.x + threadIdx.x;
    int c2n = CIN >> 1;
    int total = 27 * COUT * c2n;
    if (i >= total) return;
    int c2 = i % c2n;
    int rest = i / c2n;
    int oc = rest % COUT, k = rest / COUT;
    dst[(k * COUT + oc) * PITCH + c2] =
        f2b2(W[(k * CIN + 2 * c2) * COUT + oc],
             W[(k * CIN + 2 * c2 + 1) * COUT + oc]);
}

// Pack x [N*8 fp32] -> bf16x2 [N*4]
__global__ void pack_x(const float* __restrict__ x, unsigned* __restrict__ dst,
                       int n4) {
    int i = blockIdx.x * blockDim.x + threadIdx.x;
    if (i >= n4) return;
    float2 v = reinterpret_cast<const float2*>(x)[i];
    dst[i] = f2b2(v.x, v.y);
}

// ---------------------------------------------------------------------------
// Warp-per-voxel (x ILP) sparse conv, packed bf16 HFMA2 inner product.
//  COUT==32: lane = oc, full CIN per lane.
//  COUT==8 : lane -> (oc=lane&7, Cin slice lane>>3), shfl_xor reduce.
// EPI: 0 none; 1: out = xres - conv (8ch); 2: out = tile(xres) + conv (32ch).
// ---------------------------------------------------------------------------
template <int CIN, int COUT, int EPI, int TB, int MINB, int ILP, bool OUTBF>
__global__ void __launch_bounds__(TB, MINB)
conv_kernel(const unsigned* __restrict__ in,     // bf16x2, CIN/2 words/voxel
            const unsigned* __restrict__ WP,
            const float* __restrict__ xres,
            void* __restrict__ out, int N) {
    constexpr int csn   = (COUT == 32) ? CIN : (CIN / 4);
    constexpr int PITCH = (CIN == 8) ? 8 : 20;
    extern __shared__ unsigned Ws[];  // [27][COUT][PITCH]

    const int tid = threadIdx.x;
    for (int i = tid; i < 27 * COUT * PITCH; i += blockDim.x)
        Ws[i] = WP[i];
    __syncthreads();

    const int lane = tid & 31;
    const int warp = tid >> 5;
    const int wpb  = blockDim.x >> 5;

    int oc, cs0;
    if (COUT == 32) { oc = lane; cs0 = 0; }
    else            { oc = lane & 7; cs0 = (lane >> 3) * csn; }

    const int gw      = blockIdx.x * wpb + warp;
    const int gstride = gridDim.x * wpb;

    for (int base = gw * ILP; base < N; base += gstride * ILP) {
        int4 L[ILP];
#pragma unroll
        for (int j = 0; j < ILP; j++) {
            int n = base + j;
            L[j] = (n < N)
                 ? *reinterpret_cast<const int4*>(&g_l8[(size_t)n * 8])
                 : make_int4(0, 0, 0, 0);
        }
#pragma unroll
        for (int j = 0; j < ILP; j++) {
            const int n = base + j;
            if (n >= N) break;
            const int cnt = ((unsigned)L[j].x) >> 27;

            __nv_bfloat162 z = __float2bfloat162_rn(0.f);
            __nv_bfloat162 b0 = z, b1 = z, b2 = z, b3 = z;

            auto do_entry = [&](int e) {
                const int k   = (e >> 20) & 31;
                const int src = e & 0xFFFFF;
                const unsigned* gp = in + (size_t)src * (CIN / 2) + (cs0 >> 1);
                const unsigned* wrow =
                    &Ws[(k * COUT + oc) * PITCH + (cs0 >> 1)];
                if constexpr (csn == 2) {
                    b0 = __hfma2(u2b(gp[0]), u2b(wrow[0]), b0);
                } else {
#pragma unroll
                    for (int b = 0; b < csn / 8; b++) {
                        uint4 gv = reinterpret_cast<const uint4*>(gp)[b];
                        uint4 wv = reinterpret_cast<const uint4*>(wrow)[b];
                        b0 = __hfma2(u2b(gv.x), u2b(wv.x), b0);
                        b1 = __hfma2(u2b(gv.y), u2b(wv.y), b1);
                        b2 = __hfma2(u2b(gv.z), u2b(wv.z), b2);
                        b3 = __hfma2(u2b(gv.w), u2b(wv.w), b3);
                    }
                }
            };

            do_entry((13 << 20) | n);                 // center tap
            if (cnt > 0) do_entry(L[j].x & 0x07FFFFFF);
            if (cnt > 1) do_entry(L[j].y);
            if (cnt > 2) do_entry(L[j].z);
            if (cnt > 3) do_entry(L[j].w);
            if (cnt > 4) {
                int4 M = *reinterpret_cast<const int4*>(&g_l8[(size_t)n * 8 + 4]);
                do_entry(M.x);
                if (cnt > 5) do_entry(M.y);
                if (cnt > 6) do_entry(M.z);
                if (cnt > 7) do_entry(M.w);
#pragma unroll 1
                for (int i = 8; i < cnt; i++)
                    do_entry(g_lov[(size_t)n * LOV + i - 8]);
            }

            // fp32 reduction of the 4 bf16x2 accumulators
            float2 f0 = bf2f(*reinterpret_cast<unsigned*>(&b0));
            float2 f1 = bf2f(*reinterpret_cast<unsigned*>(&b1));
            float2 f2 = bf2f(*reinterpret_cast<unsigned*>(&b2));
            float2 f3 = bf2f(*reinterpret_cast<unsigned*>(&b3));
            float acc = ((f0.x + f0.y) + (f1.x + f1.y))
                      + ((f2.x + f2.y) + (f3.x + f3.y));

            if constexpr (COUT == 8) {
                acc += __shfl_xor_sync(0xffffffffu, acc, 8);
                acc += __shfl_xor_sync(0xffffffffu, acc, 16);
                float v = acc;
                if constexpr (EPI == 1)
                    v = xres[(size_t)n * 8 + (lane & 7)] - v;
                if constexpr (OUTBF) {
                    float pv = __shfl_xor_sync(0xffffffffu, v, 1);
                    if (lane < 8 && (lane & 1) == 0)
                        ((unsigned*)out)[(size_t)n * 4 + (lane >> 1)] = f2b2(v, pv);
                } else {
                    if (lane < 8)
                        ((float*)out)[(size_t)n * 8 + lane] = v;
                }
            } else {
                float v = acc;
                if constexpr (EPI == 2)
                    v += xres[(size_t)n * 8 + (lane & 7)];
                if constexpr (OUTBF) {
                    float pv = __shfl_xor_sync(0xffffffffu, v, 1);
                    if ((lane & 1) == 0)
                        ((unsigned*)out)[(size_t)n * 16 + (lane >> 1)] = f2b2(v, pv);
                } else {
                    ((float*)out)[(size_t)n * 32 + lane] = v;
                }
            }
        }
    }
}

// ---------------------------------------------------------------------------
extern "C" void kernel_launch(void* const* d_in, const int* in_sizes, int n_in,
                              void* d_out, int out_size) {
    const float* x    = (const float*)d_in[0];
    const int*   nbr  = (const int*)d_in[1];
    const void*  mask = (const void*)d_in[2];
    const float* Wd0  = (const float*)d_in[3];
    const float* Wd1  = (const float*)d_in[4];
    const float* Wd2  = (const float*)d_in[5];
    const float* Wu0  = (const float*)d_in[6];
    const float* Wu1  = (const float*)d_in[7];
    const float* Wu2  = (const float*)d_in[8];
    float*       out  = (float*)d_out;
    const int N = in_sizes[0] / 8;

    unsigned *xbf, *t32, *t8a, *t8b, *wp;
    float* wfold;
    cudaGetSymbolAddress((void**)&xbf,   g_xbf);
    cudaGetSymbolAddress((void**)&t32,   g_t32p);
    cudaGetSymbolAddress((void**)&t8a,   g_t8ap);
    cudaGetSymbolAddress((void**)&t8b,   g_t8bp);
    cudaGetSymbolAddress((void**)&wfold, g_wfold);
    cudaGetSymbolAddress((void**)&wp,    g_wpack);

    const int sm_8_32  = 6912  * 4;
    const int sm_32_8  = 4320  * 4;
    const int sm_8_8   = 1728  * 4;
    const int sm_32_32 = 17280 * 4;   // 69,120 B

    cudaFuncSetAttribute(
        (const void*)conv_kernel<32, 32, 2, 512, 2, 1, false>,
        cudaFuncAttributeMaxDynamicSharedMemorySize, sm_32_32);

    detect_mask<<<1, 256>>>((const unsigned int*)mask);
    build_compact<<<(N + 255) / 256, 256>>>(nbr, mask, N);
    fold_wd0<<<(27 * 8 * 32 + 255) / 256, 256>>>(Wd0);
    pack_x<<<(N * 4 + 255) / 256, 256>>>(x, xbf, N * 4);

    pack_w<<<(27 * 32 * 4  + 255) / 256, 256>>>(wfold, wp + WQ0,  8, 32,  8);
    pack_w<<<(27 * 8  * 16 + 255) / 256, 256>>>(Wd1,   wp + WQ1, 32,  8, 20);
    pack_w<<<(27 * 8  * 4  + 255) / 256, 256>>>(Wd2,   wp + WQ2,  8,  8,  8);
    pack_w<<<(27 * 8  * 4  + 255) / 256, 256>>>(Wu0,   wp + WQ3,  8,  8,  8);
    pack_w<<<(27 * 32 * 4  + 255) / 256, 256>>>(Wu1,   wp + WQ4,  8, 32,  8);
    pack_w<<<(27 * 32 * 16 + 255) / 256, 256>>>(Wu2,   wp + WQ5, 32, 32, 20);

    // K1: 8 -> 32 (tile folded into wfold)
    conv_kernel<8, 32, 0, 256, 6, 2, true>
        <<<NSM * 6, 256, sm_8_32>>>(xbf, wp + WQ0, x, t32, N);
    // K2: 32 -> 8
    conv_kernel<32, 8, 0, 256, 6, 2, true>
        <<<NSM * 6, 256, sm_32_8>>>(t32, wp + WQ1, x, t8a, N);
    // K3: 8 -> 8, epilogue r = x - d
    conv_kernel<8, 8, 1, 256, 6, 2, true>
        <<<NSM * 6, 256, sm_8_8>>>(t8a, wp + WQ2, x, t8b, N);
    // K4: 8 -> 8
    conv_kernel<8, 8, 0, 256, 6, 2, true>
        <<<NSM * 6, 256, sm_8_8>>>(t8b, wp + WQ3, x, t8a, N);
    // K5: 8 -> 32
    conv_kernel<8, 32, 0, 256, 6, 2, true>
        <<<NSM * 6, 256, sm_8_32>>>(t8a, wp + WQ4, x, t32, N);
    // K6: 32 -> 32, epilogue out = tile(x) + conv (fp32 out)
    conv_kernel<32, 32, 2, 512, 2, 1, false>
        <<<NSM * 2, 512, sm_32_32>>>(t32, wp + WQ5, x, out, N);
}

// round 11
// speedup vs baseline: 1.6529x; 1.0260x over previous
#include <cuda_runtime.h>
#include <cuda_bf16.h>
#include <cstdint>

// ---------------------------------------------------------------------------
// Sparse 3x3x3 conv chain, N=1e6 voxels. R11 = R10 +
//  * K6 ILP=2 (2 independent voxel chains/warp at same occupancy)
//  * K3/K4 ILP=4 (batched list loads dominate tiny csn=2 work)
//  * merged weight-pack kernel, wide detect_mask, K3 residual from bf16 x
// ---------------------------------------------------------------------------

#define MAXN 1000000
#define NSM  148
#define LOV  20

__device__ int      g_mtype;
__device__ int      g_l8[(size_t)MAXN * 8];    // entries 0..7 (e0 carries cnt)
__device__ int      g_lov[(size_t)MAXN * LOV]; // entries 8.. (rare)
__device__ unsigned g_xbf[(size_t)MAXN * 4];   // x as bf16x2, 8 ch
__device__ unsigned g_t32p[(size_t)MAXN * 16]; // bf16x2, 32 ch
__device__ unsigned g_t8ap[(size_t)MAXN * 4];
__device__ unsigned g_t8bp[(size_t)MAXN * 4];
__device__ float    g_wfold[27 * 8 * 32];
__device__ unsigned g_wpack[6912 + 4320 + 1728 + 1728 + 6912 + 17280];

#define WQ0 0                  // K1 <8,32>  pitch 8  : 6912
#define WQ1 (WQ0 + 6912)       // K2 <32,8>  pitch 20 : 4320
#define WQ2 (WQ1 + 4320)       // K3 <8,8>   pitch 8  : 1728
#define WQ3 (WQ2 + 1728)       // K4 <8,8>
#define WQ4 (WQ3 + 1728)       // K5 <8,32>
#define WQ5 (WQ4 + 6912)       // K6 <32,32> pitch 20 : 17280

// ---------------------------------------------------------------------------
__global__ void detect_mask(const unsigned int* __restrict__ m) {
    __shared__ int s_u8, s_f32;
    if (threadIdx.x == 0) { s_u8 = 0; s_f32 = 0; }
    __syncthreads();
    int loc_u8 = 0, loc_f32 = 0;
    for (int i = threadIdx.x; i < 65536; i += blockDim.x) {
        unsigned v = m[i];
        if (v == 0x3F800000u) loc_f32 = 1;
        else if (v > 1u)      loc_u8 = 1;
    }
    if (loc_u8)  atomicOr(&s_u8, 1);
    if (loc_f32) atomicOr(&s_f32, 1);
    __syncthreads();
    if (threadIdx.x == 0) g_mtype = s_f32 ? 2 : (s_u8 ? 1 : 0);
}

__global__ void build_compact(const int* __restrict__ nbr,
                              const void* __restrict__ maskv, int N) {
    int n = blockIdx.x * blockDim.x + threadIdx.x;
    if (n >= N) return;
    const int mt = g_mtype;
    const int*           mi = (const int*)maskv;
    const unsigned char* mb = (const unsigned char*)maskv;
    const float*         mf = (const float*)maskv;
    int cnt = 0, first = 0;
    int* lst = &g_l8[(size_t)n * 8];
#pragma unroll 1
    for (int k = 0; k < 27; k++) {
        if (k == 13) continue;
        size_t o = (size_t)k * N + n;
        bool on;
        if (mt == 0)      on = mi[o] != 0;
        else if (mt == 1) on = mb[o] != 0;
        else              on = mf[o] != 0.0f;
        if (on) {
            int e = (k << 20) | nbr[o];
            if (cnt == 0)      first = e;
            else if (cnt < 8)  lst[cnt] = e;
            else               g_lov[(size_t)n * LOV + cnt - 8] = e;
            cnt++;
        }
    }
    lst[0] = first | (cnt << 27);
    if (cnt < 2) lst[1] = 0;
    if (cnt < 3) lst[2] = 0;
    if (cnt < 4) lst[3] = 0;
}

// Fold tile(x,(1,4)) into Wd0: wfold[k][c][j] = sum_t Wd0[k][c+8t][j]
__global__ void fold_wd0(const float* __restrict__ Wd0) {
    int i = blockIdx.x * blockDim.x + threadIdx.x;
    if (i >= 27 * 8 * 32) return;
    int k = i / 256, rem = i % 256;
    int c = rem / 32, j = rem % 32;
    float s = 0.f;
#pragma unroll
    for (int t = 0; t < 4; t++) s += Wd0[k * 1024 + (c + 8 * t) * 32 + j];
    g_wfold[i] = s;
}

__device__ __forceinline__ unsigned f2b2(float lo, float hi) {
    __nv_bfloat162 p = __floats2bfloat162_rn(lo, hi);
    return *reinterpret_cast<unsigned*>(&p);
}
__device__ __forceinline__ float2 bf2f(unsigned u) {
    float2 r;
    r.x = __uint_as_float(u << 16);
    r.y = __uint_as_float(u & 0xFFFF0000u);
    return r;
}
__device__ __forceinline__ __nv_bfloat162 u2b(unsigned u) {
    return *reinterpret_cast<__nv_bfloat162*>(&u);
}

// One kernel packs all six weight sets (W[k][c][oc] fp32 -> bf16x2 rows).
__device__ __forceinline__ void pack_one(const float* W, unsigned* dst,
                                         int CIN, int COUT, int PITCH, int i) {
    int c2n = CIN >> 1;
    int c2 = i % c2n;
    int rest = i / c2n;
    int oc = rest % COUT, k = rest / COUT;
    dst[(k * COUT + oc) * PITCH + c2] =
        f2b2(W[(k * CIN + 2 * c2) * COUT + oc],
             W[(k * CIN + 2 * c2 + 1) * COUT + oc]);
}
__global__ void pack_all(const float* __restrict__ Wf,  // wfold
                         const float* __restrict__ Wd1,
                         const float* __restrict__ Wd2,
                         const float* __restrict__ Wu0,
                         const float* __restrict__ Wu1,
                         const float* __restrict__ Wu2,
                         unsigned* __restrict__ wp) {
    int i = blockIdx.x * blockDim.x + threadIdx.x;
    // segment sizes (work items = 27*COUT*CIN/2)
    const int s0 = 3456, s1 = 3456, s2 = 864, s3 = 864, s4 = 3456, s5 = 13824;
    if (i < s0) { pack_one(Wf,  wp + WQ0,  8, 32,  8, i); return; }
    i -= s0;
    if (i < s1) { pack_one(Wd1, wp + WQ1, 32,  8, 20, i); return; }
    i -= s1;
    if (i < s2) { pack_one(Wd2, wp + WQ2,  8,  8,  8, i); return; }
    i -= s2;
    if (i < s3) { pack_one(Wu0, wp + WQ3,  8,  8,  8, i); return; }
    i -= s3;
    if (i < s4) { pack_one(Wu1, wp + WQ4,  8, 32,  8, i); return; }
    i -= s4;
    if (i < s5) { pack_one(Wu2, wp + WQ5, 32, 32, 20, i); return; }
}

// Pack x [N*8 fp32] -> bf16x2 [N*4]
__global__ void pack_x(const float* __restrict__ x, unsigned* __restrict__ dst,
                       int n4) {
    int i = blockIdx.x * blockDim.x + threadIdx.x;
    if (i >= n4) return;
    float2 v = reinterpret_cast<const float2*>(x)[i];
    dst[i] = f2b2(v.x, v.y);
}

// ---------------------------------------------------------------------------
// Warp-per-voxel (x ILP) sparse conv, packed bf16 HFMA2 inner product.
// EPI: 0 none; 1: out = xres - conv (8ch, xres bf16); 2: out = tile(xres fp32)
//      + conv (32ch).
// ---------------------------------------------------------------------------
template <int CIN, int COUT, int EPI, int TB, int MINB, int ILP, bool OUTBF>
__global__ void __launch_bounds__(TB, MINB)
conv_kernel(const unsigned* __restrict__ in,     // bf16x2, CIN/2 words/voxel
            const unsigned* __restrict__ WP,
            const void* __restrict__ xres,       // fp32 (EPI2) or bf16x2 (EPI1)
            void* __restrict__ out, int N) {
    constexpr int csn   = (COUT == 32) ? CIN : (CIN / 4);
    constexpr int PITCH = (CIN == 8) ? 8 : 20;
    extern __shared__ unsigned Ws[];  // [27][COUT][PITCH]

    const int tid = threadIdx.x;
    for (int i = tid; i < 27 * COUT * PITCH; i += blockDim.x)
        Ws[i] = WP[i];
    __syncthreads();

    const int lane = tid & 31;
    const int warp = tid >> 5;
    const int wpb  = blockDim.x >> 5;

    int oc, cs0;
    if (COUT == 32) { oc = lane; cs0 = 0; }
    else            { oc = lane & 7; cs0 = (lane >> 3) * csn; }

    const int gw      = blockIdx.x * wpb + warp;
    const int gstride = gridDim.x * wpb;

    for (int base = gw * ILP; base < N; base += gstride * ILP) {
        int4 L[ILP];
#pragma unroll
        for (int j = 0; j < ILP; j++) {
            int n = base + j;
            L[j] = (n < N)
                 ? *reinterpret_cast<const int4*>(&g_l8[(size_t)n * 8])
                 : make_int4(0, 0, 0, 0);
        }
#pragma unroll
        for (int j = 0; j < ILP; j++) {
            const int n = base + j;
            if (n >= N) break;
            const int cnt = ((unsigned)L[j].x) >> 27;

            __nv_bfloat162 z = __float2bfloat162_rn(0.f);
            __nv_bfloat162 b0 = z, b1 = z, b2 = z, b3 = z;

            auto do_entry = [&](int e) {
                const int k   = (e >> 20) & 31;
                const int src = e & 0xFFFFF;
                const unsigned* gp = in + (size_t)src * (CIN / 2) + (cs0 >> 1);
                const unsigned* wrow =
                    &Ws[(k * COUT + oc) * PITCH + (cs0 >> 1)];
                if constexpr (csn == 2) {
                    b0 = __hfma2(u2b(gp[0]), u2b(wrow[0]), b0);
                } else {
#pragma unroll
                    for (int b = 0; b < csn / 8; b++) {
                        uint4 gv = reinterpret_cast<const uint4*>(gp)[b];
                        uint4 wv = reinterpret_cast<const uint4*>(wrow)[b];
                        b0 = __hfma2(u2b(gv.x), u2b(wv.x), b0);
                        b1 = __hfma2(u2b(gv.y), u2b(wv.y), b1);
                        b2 = __hfma2(u2b(gv.z), u2b(wv.z), b2);
                        b3 = __hfma2(u2b(gv.w), u2b(wv.w), b3);
                    }
                }
            };

            do_entry((13 << 20) | n);                 // center tap
            if (cnt > 0) do_entry(L[j].x & 0x07FFFFFF);
            if (cnt > 1) do_entry(L[j].y);
            if (cnt > 2) do_entry(L[j].z);
            if (cnt > 3) do_entry(L[j].w);
            if (cnt > 4) {
                int4 M = *reinterpret_cast<const int4*>(&g_l8[(size_t)n * 8 + 4]);
                do_entry(M.x);
                if (cnt > 5) do_entry(M.y);
                if (cnt > 6) do_entry(M.z);
                if (cnt > 7) do_entry(M.w);
#pragma unroll 1
                for (int i = 8; i < cnt; i++)
                    do_entry(g_lov[(size_t)n * LOV + i - 8]);
            }

            float2 f0 = bf2f(*reinterpret_cast<unsigned*>(&b0));
            float2 f1 = bf2f(*reinterpret_cast<unsigned*>(&b1));
            float2 f2 = bf2f(*reinterpret_cast<unsigned*>(&b2));
            float2 f3 = bf2f(*reinterpret_cast<unsigned*>(&b3));
            float acc = ((f0.x + f0.y) + (f1.x + f1.y))
                      + ((f2.x + f2.y) + (f3.x + f3.y));

            if constexpr (COUT == 8) {
                acc += __shfl_xor_sync(0xffffffffu, acc, 8);
                acc += __shfl_xor_sync(0xffffffffu, acc, 16);
                float v = acc;
                if constexpr (EPI == 1) {
                    // xres is bf16x2 (8 ch): lane reads its channel
                    unsigned xp = ((const unsigned*)xres)
                                      [(size_t)n * 4 + ((lane & 7) >> 1)];
                    float2 xv = bf2f(xp);
                    v = ((lane & 1) ? xv.y : xv.x) - v;
                }
                if constexpr (OUTBF) {
                    float pv = __shfl_xor_sync(0xffffffffu, v, 1);
                    if (lane < 8 && (lane & 1) == 0)
                        ((unsigned*)out)[(size_t)n * 4 + (lane >> 1)] = f2b2(v, pv);
                } else {
                    if (lane < 8)
                        ((float*)out)[(size_t)n * 8 + lane] = v;
                }
            } else {
                float v = acc;
                if constexpr (EPI == 2)
                    v += ((const float*)xres)[(size_t)n * 8 + (lane & 7)];
                if constexpr (OUTBF) {
                    float pv = __shfl_xor_sync(0xffffffffu, v, 1);
                    if ((lane & 1) == 0)
                        ((unsigned*)out)[(size_t)n * 16 + (lane >> 1)] = f2b2(v, pv);
                } else {
                    ((float*)out)[(size_t)n * 32 + lane] = v;
                }
            }
        }
    }
}

// ---------------------------------------------------------------------------
extern "C" void kernel_launch(void* const* d_in, const int* in_sizes, int n_in,
                              void* d_out, int out_size) {
    const float* x    = (const float*)d_in[0];
    const int*   nbr  = (const int*)d_in[1];
    const void*  mask = (const void*)d_in[2];
    const float* Wd0  = (const float*)d_in[3];
    const float* Wd1  = (const float*)d_in[4];
    const float* Wd2  = (const float*)d_in[5];
    const float* Wu0  = (const float*)d_in[6];
    const float* Wu1  = (const float*)d_in[7];
    const float* Wu2  = (const float*)d_in[8];
    float*       out  = (float*)d_out;
    const int N = in_sizes[0] / 8;

    unsigned *xbf, *t32, *t8a, *t8b, *wp;
    float* wfold;
    cudaGetSymbolAddress((void**)&xbf,   g_xbf);
    cudaGetSymbolAddress((void**)&t32,   g_t32p);
    cudaGetSymbolAddress((void**)&t8a,   g_t8ap);
    cudaGetSymbolAddress((void**)&t8b,   g_t8bp);
    cudaGetSymbolAddress((void**)&wfold, g_wfold);
    cudaGetSymbolAddress((void**)&wp,    g_wpack);

    const int sm_8_32  = 6912  * 4;
    const int sm_32_8  = 4320  * 4;
    const int sm_8_8   = 1728  * 4;
    const int sm_32_32 = 17280 * 4;   // 69,120 B

    cudaFuncSetAttribute(
        (const void*)conv_kernel<32, 32, 2, 512, 2, 2, false>,
        cudaFuncAttributeMaxDynamicSharedMemorySize, sm_32_32);

    detect_mask<<<1, 1024>>>((const unsigned int*)mask);
    build_compact<<<(N + 255) / 256, 256>>>(nbr, mask, N);
    fold_wd0<<<(27 * 8 * 32 + 255) / 256, 256>>>(Wd0);
    pack_x<<<(N * 4 + 255) / 256, 256>>>(x, xbf, N * 4);
    pack_all<<<(3456 * 3 + 864 * 2 + 13824 + 255) / 256, 256>>>(
        wfold, Wd1, Wd2, Wu0, Wu1, Wu2, wp);

    // K1: 8 -> 32 (tile folded into wfold)
    conv_kernel<8, 32, 0, 256, 6, 2, true>
        <<<NSM * 6, 256, sm_8_32>>>(xbf, wp + WQ0, x, t32, N);
    // K2: 32 -> 8
    conv_kernel<32, 8, 0, 256, 6, 2, true>
        <<<NSM * 6, 256, sm_32_8>>>(t32, wp + WQ1, x, t8a, N);
    // K3: 8 -> 8, epilogue r = x(bf16) - d
    conv_kernel<8, 8, 1, 256, 6, 4, true>
        <<<NSM * 6, 256, sm_8_8>>>(t8a, wp + WQ2, xbf, t8b, N);
    // K4: 8 -> 8
    conv_kernel<8, 8, 0, 256, 6, 4, true>
        <<<NSM * 6, 256, sm_8_8>>>(t8b, wp + WQ3, x, t8a, N);
    // K5: 8 -> 32
    conv_kernel<8, 32, 0, 256, 6, 2, true>
        <<<NSM * 6, 256, sm_8_32>>>(t8a, wp + WQ4, x, t32, N);
    // K6: 32 -> 32, epilogue out = tile(x fp32) + conv; ILP=2
    conv_kernel<32, 32, 2, 512, 2, 2, false>
        <<<NSM * 2, 512, sm_32_32>>>(t32, wp + WQ5, x, out, N);
}